// round 15
// baseline (speedup 1.0000x reference)
#include <cuda_runtime.h>
#include <cuda_fp16.h>

#define SB   2
#define CIN  32
#define COUT 64
#define RANK 64
#define S    64
#define PVOL (S*S*S)   // 262144

// Scratch (alloc-free rule: device globals). fp16: 67 MB each.
__device__ __half g_bufA[(size_t)SB * RANK * PVOL];
__device__ __half g_bufB[(size_t)SB * RANK * PVOL];

// ---------------------------------------------------------------------------
// helpers
// ---------------------------------------------------------------------------
__device__ __forceinline__ unsigned f2tf(float f) {
    unsigned u;
    asm("cvt.rna.tf32.f32 %0, %1;" : "=r"(u) : "f"(f));
    return u;
}

__device__ __forceinline__ void mma_tf32(float c[4], const unsigned a[4],
                                         const unsigned b0, const unsigned b1) {
    asm volatile(
        "mma.sync.aligned.m16n8k8.row.col.f32.tf32.tf32.f32 "
        "{%0,%1,%2,%3}, {%4,%5,%6,%7}, {%8,%9}, {%0,%1,%2,%3};"
        : "+f"(c[0]), "+f"(c[1]), "+f"(c[2]), "+f"(c[3])
        : "r"(a[0]), "r"(a[1]), "r"(a[2]), "r"(a[3]), "r"(b0), "r"(b1));
}

__device__ __forceinline__ void mma_f16(float c[4], const unsigned a[4],
                                        const unsigned b0, const unsigned b1) {
    asm volatile(
        "mma.sync.aligned.m16n8k16.row.col.f32.f16.f16.f32 "
        "{%0,%1,%2,%3}, {%4,%5,%6,%7}, {%8,%9}, {%0,%1,%2,%3};"
        : "+f"(c[0]), "+f"(c[1]), "+f"(c[2]), "+f"(c[3])
        : "r"(a[0]), "r"(a[1]), "r"(a[2]), "r"(a[3]), "r"(b0), "r"(b1));
}

__device__ __forceinline__ void ldsm_x4_trans(unsigned& r0, unsigned& r1,
                                              unsigned& r2, unsigned& r3,
                                              unsigned saddr) {
    asm volatile(
        "ldmatrix.sync.aligned.m8n8.x4.trans.shared.b16 {%0,%1,%2,%3}, [%4];"
        : "=r"(r0), "=r"(r1), "=r"(r2), "=r"(r3) : "r"(saddr));
}

// L2 policies
__device__ __forceinline__ unsigned long long pol_ef() {
    unsigned long long p;
    asm("createpolicy.fractional.L2::evict_first.b64 %0, 1.0;" : "=l"(p));
    return p;
}
__device__ __forceinline__ unsigned long long pol_el() {
    unsigned long long p;
    asm("createpolicy.fractional.L2::evict_last.b64 %0, 1.0;" : "=l"(p));
    return p;
}

// cp.async with explicit src-size + L2 cache policy
__device__ __forceinline__ void cp_async16h(unsigned saddr, const void* gptr,
                                            int sz, unsigned long long pol) {
    asm volatile(
        "cp.async.cg.shared.global.L2::cache_hint [%0], [%1], 16, %2, %3;\n"
        :: "r"(saddr), "l"(gptr), "r"(sz), "l"(pol));
}
__device__ __forceinline__ void cp_commit() {
    asm volatile("cp.async.commit_group;\n");
}
__device__ __forceinline__ void cp_wait0() {
    asm volatile("cp.async.wait_group 0;\n");
}
__device__ __forceinline__ void cp_wait1() {
    asm volatile("cp.async.wait_group 1;\n");
}

// policy-register stores (cache_hint form — valid for all widths)
__device__ __forceinline__ void st_b32_pol(void* addr, unsigned v,
                                           unsigned long long pol) {
    asm volatile("st.global.L2::cache_hint.b32 [%0], %1, %2;"
                 :: "l"(addr), "r"(v), "l"(pol));
}
__device__ __forceinline__ void st_b64_pol(void* addr, unsigned long long v,
                                           unsigned long long pol) {
    asm volatile("st.global.L2::cache_hint.b64 [%0], %1, %2;"
                 :: "l"(addr), "l"(v), "l"(pol));
}
__device__ __forceinline__ void st_f2_pol(void* addr, float a, float b,
                                          unsigned long long pol) {
    asm volatile("st.global.L2::cache_hint.v2.f32 [%0], {%1, %2}, %3;"
                 :: "l"(addr), "f"(a), "f"(b), "l"(pol));
}

// ---------------------------------------------------------------------------
// K1 (tf32, 2-stage cp.async, 4 tiles/block — R13 form, reg-capped for occ 4)
// y[b,r,p] = sum_c Win[c,r] * x[b,c,p] -> fp16 (evict_last)
// ---------------------------------------------------------------------------
__global__ void __launch_bounds__(256, 4) k1_mma(const float* __restrict__ x,
                                                 const float* __restrict__ Win) {
    __shared__ unsigned sW[CIN * 72];      // tf32 weights [c][r], ld=72
    __shared__ unsigned sX[2][CIN * 136];  // raw fp32 bits x tiles [c][p]

    int b      = blockIdx.x >> 9;
    int p_base = (blockIdx.x & 511) << 9;   // 4 tiles x 128
    int t      = threadIdx.x;

    unsigned long long pef = pol_ef();
    unsigned long long pel = pol_el();
    const float* xb = x + (size_t)b * CIN * PVOL;

    {
        unsigned sa = (unsigned)__cvta_generic_to_shared(&sX[0][0]);
        #pragma unroll
        for (int i = 0; i < 4; i++) {
            int idx = t + 256 * i;
            int c = idx >> 5, j = idx & 31;
            cp_async16h(sa + (c * 136 + 4 * j) * 4,
                        xb + (size_t)c * PVOL + p_base + 4 * j, 16, pef);
        }
        cp_commit();
    }

    {
        const float4* W4 = (const float4*)Win;
        for (int i = t; i < CIN * RANK / 4; i += 256) {
            int c = i >> 4, r4 = i & 15;
            float4 v = W4[i];
            unsigned* dst = &sW[c * 72 + 4 * r4];
            dst[0] = f2tf(v.x); dst[1] = f2tf(v.y);
            dst[2] = f2tf(v.z); dst[3] = f2tf(v.w);
        }
    }
    cp_wait0();
    __syncthreads();

    int lane = t & 31, wid = t >> 5;
    int g = lane >> 2, tg = lane & 3;
    int r0 = (wid & 1) * 32;       // M offset: 2 groups of 32 ranks
    int pW = (wid >> 1) * 32;      // N offset: 4 groups of 32 positions

    unsigned A[4][2][4];
    #pragma unroll
    for (int ks = 0; ks < 4; ks++)
        #pragma unroll
        for (int mm = 0; mm < 2; mm++) {
            int rm = r0 + 16 * mm;
            A[ks][mm][0] = sW[(ks * 8 + tg) * 72 + rm + g];
            A[ks][mm][1] = sW[(ks * 8 + tg) * 72 + rm + g + 8];
            A[ks][mm][2] = sW[(ks * 8 + tg + 4) * 72 + rm + g];
            A[ks][mm][3] = sW[(ks * 8 + tg + 4) * 72 + rm + g + 8];
        }

    #pragma unroll
    for (int tt = 0; tt < 4; tt++) {
        int p0 = p_base + tt * 128;
        const unsigned* cur = sX[tt & 1];

        if (tt < 3) {
            unsigned sa = (unsigned)__cvta_generic_to_shared(&sX[(tt + 1) & 1][0]);
            #pragma unroll
            for (int i = 0; i < 4; i++) {
                int idx = t + 256 * i;
                int c = idx >> 5, j = idx & 31;
                cp_async16h(sa + (c * 136 + 4 * j) * 4,
                            xb + (size_t)c * PVOL + p0 + 128 + 4 * j, 16, pef);
            }
            cp_commit();
        }

        float C[2][4][4];
        #pragma unroll
        for (int mm = 0; mm < 2; mm++)
            #pragma unroll
            for (int ni = 0; ni < 4; ni++)
                #pragma unroll
                for (int q = 0; q < 4; q++) C[mm][ni][q] = 0.0f;

        #pragma unroll
        for (int ks = 0; ks < 4; ks++) {
            #pragma unroll
            for (int ni = 0; ni < 4; ni++) {
                unsigned b0 = cur[(ks * 8 + tg) * 136 + pW + 8 * ni + g];
                unsigned b1 = cur[(ks * 8 + tg + 4) * 136 + pW + 8 * ni + g];
                mma_tf32(C[0][ni], A[ks][0], b0, b1);
                mma_tf32(C[1][ni], A[ks][1], b0, b1);
            }
        }

        #pragma unroll
        for (int mm = 0; mm < 2; mm++)
            #pragma unroll
            for (int ni = 0; ni < 4; ni++) {
                int p = p0 + pW + 8 * ni + 2 * tg;
                int rm = r0 + 16 * mm;
                size_t o0 = (size_t)(b * RANK + rm + g) * PVOL + p;
                size_t o1 = (size_t)(b * RANK + rm + g + 8) * PVOL + p;
                __half2 v0 = __floats2half2_rn(C[mm][ni][0], C[mm][ni][1]);
                __half2 v1 = __floats2half2_rn(C[mm][ni][2], C[mm][ni][3]);
                st_b32_pol(&g_bufA[o0], *(unsigned*)&v0, pel);
                st_b32_pol(&g_bufA[o1], *(unsigned*)&v1, pel);
            }

        if (tt < 3) {
            cp_wait0();
            __syncthreads();
        }
    }
}

// ---------------------------------------------------------------------------
// K23 (streaming, cp.async ring, shuffle d-tap, L2 hints): fp16 planes.
// ---------------------------------------------------------------------------
__global__ void __launch_bounds__(256) k23_stream(const float* __restrict__ Uh,
                                                  const float* __restrict__ Uw,
                                                  const float* __restrict__ Ud) {
    extern __shared__ float dsm[];
    __half* raw = (__half*)dsm;            // 3 planes x 4096 halves
    float* hq  = dsm + 3 * 4096 / 2;       // 64*68 fp32

    int blk = blockIdx.x;
    int hc = blk & 7;
    int r  = (blk >> 3) & 63;
    int b  = blk >> 9;
    int h0 = hc * 8;
    size_t rbase = (size_t)(b * RANK + r) * PVOL;
    int t = threadIdx.x;

    unsigned long long pef = pol_ef();
    unsigned long long pel = pol_el();

    float uh0 = __ldg(&Uh[r]), uh1 = __ldg(&Uh[64 + r]), uh2 = __ldg(&Uh[128 + r]);
    float uw0 = __ldg(&Uw[r]), uw1 = __ldg(&Uw[64 + r]), uw2 = __ldg(&Uw[128 + r]);
    float ud0 = __ldg(&Ud[r]), ud1 = __ldg(&Ud[64 + r]), ud2 = __ldg(&Ud[128 + r]);

    const float4 z4 = make_float4(0.f, 0.f, 0.f, 0.f);
    unsigned raw_sa = (unsigned)__cvta_generic_to_shared(raw);

    #pragma unroll
    for (int k = -1; k <= 1; k++) {
        int hp = h0 + k;
        int slot = (hp + 3) % 3;
        int sz = (hp >= 0 && hp < 64) ? 16 : 0;
        const __half* src = g_bufA + rbase + (size_t)hp * 4096;
        #pragma unroll
        for (int i = 0; i < 2; i++) {
            int q = t + i * 256;
            cp_async16h(raw_sa + (slot * 4096 + q * 8) * 2, src + q * 8, sz, pef);
        }
    }
    cp_commit();
    cp_wait0();
    __syncthreads();

    for (int hh = 0; hh < 8; hh++) {
        int h = h0 + hh;
        int sm_ = (h + 2) % 3;
        int s0  = h % 3;
        int sp  = (h + 1) % 3;

        // h-tap: raw(fp16) -> hq(fp32)
        #pragma unroll
        for (int i = 0; i < 4; i++) {
            int q = t + i * 256;
            int w = q >> 4, d4 = q & 15;
            __half2 m01 = *(__half2*)&raw[sm_ * 4096 + q * 4];
            __half2 m23 = *(__half2*)&raw[sm_ * 4096 + q * 4 + 2];
            __half2 c01 = *(__half2*)&raw[s0  * 4096 + q * 4];
            __half2 c23 = *(__half2*)&raw[s0  * 4096 + q * 4 + 2];
            __half2 p01 = *(__half2*)&raw[sp  * 4096 + q * 4];
            __half2 p23 = *(__half2*)&raw[sp  * 4096 + q * 4 + 2];
            float2 mA = __half22float2(m01), mB = __half22float2(m23);
            float2 cA = __half22float2(c01), cB = __half22float2(c23);
            float2 pA = __half22float2(p01), pB = __half22float2(p23);
            float4 o;
            o.x = uh0 * mA.x + uh1 * cA.x + uh2 * pA.x;
            o.y = uh0 * mA.y + uh1 * cA.y + uh2 * pA.y;
            o.z = uh0 * mB.x + uh1 * cB.x + uh2 * pB.x;
            o.w = uh0 * mB.y + uh1 * cB.y + uh2 * pB.y;
            *(float4*)&hq[w * 68 + d4 * 4] = o;
        }
        __syncthreads();   // hq ready; raw[sm_] now free

        if (hh < 7) {
            int hn = h + 2;
            int sz = (hn < 64) ? 16 : 0;
            const __half* src = g_bufA + rbase + (size_t)hn * 4096;
            #pragma unroll
            for (int i = 0; i < 2; i++) {
                int q = t + i * 256;
                cp_async16h(raw_sa + (sm_ * 4096 + q * 8) * 2, src + q * 8, sz, pef);
            }
            cp_commit();
        }

        // w-tap (regs) + shuffle d-tap -> fp16 gmem (evict_last)
        __half* Bo = g_bufB + rbase + (size_t)h * 4096;
        #pragma unroll
        for (int i = 0; i < 4; i++) {
            int q = t + i * 256;
            int w = q >> 4, d4 = q & 15;
            float4 c0 = *(const float4*)&hq[w * 68 + d4 * 4];
            float4 m = z4, p = z4;
            if (w > 0)  m = *(const float4*)&hq[(w - 1) * 68 + d4 * 4];
            if (w < 63) p = *(const float4*)&hq[(w + 1) * 68 + d4 * 4];
            float4 f;
            f.x = uw0 * m.x + uw1 * c0.x + uw2 * p.x;
            f.y = uw0 * m.y + uw1 * c0.y + uw2 * p.y;
            f.z = uw0 * m.z + uw1 * c0.z + uw2 * p.z;
            f.w = uw0 * m.w + uw1 * c0.w + uw2 * p.w;

            float lft = __shfl_up_sync(0xffffffffu, f.w, 1);
            float rgt = __shfl_down_sync(0xffffffffu, f.x, 1);
            if (d4 == 0)  lft = 0.f;
            if (d4 == 15) rgt = 0.f;

            __half2 lo = __floats2half2_rn(ud0 * lft + ud1 * f.x + ud2 * f.y,
                                           ud0 * f.x + ud1 * f.y + ud2 * f.z);
            __half2 hi = __floats2half2_rn(ud0 * f.y + ud1 * f.z + ud2 * f.w,
                                           ud0 * f.z + ud1 * f.w + ud2 * rgt);
            unsigned long long pk =
                (unsigned long long)(*(unsigned*)&lo) |
                ((unsigned long long)(*(unsigned*)&hi) << 32);
            st_b64_pol(&Bo[q * 4], pk, pel);
        }

        if (hh < 7) cp_wait0();
        __syncthreads();   // raw slot refilled; hq reads done
    }
}

// ---------------------------------------------------------------------------
// K4 (fp16 HMMA + ldmatrix, 3-stage cp.async — R13 form, reg-capped for occ 3)
// out = Uout^T * t + bias
// ---------------------------------------------------------------------------
__global__ void __launch_bounds__(256, 3) k4_mma(const float* __restrict__ Uout,
                                                 const float* __restrict__ bias,
                                                 float* __restrict__ out) {
    extern __shared__ __half hsm[];
    __half* sA = hsm;                  // [co=64][r], ld=72 halves
    __half* sT = hsm + 64 * 72;        // 3 tile buffers [r][p], ld=136

    int b      = blockIdx.x >> 9;
    int p_base = (blockIdx.x & 511) << 9;
    int t      = threadIdx.x;

    unsigned long long pef = pol_ef();
    const __half* Tbase = g_bufB + (size_t)b * RANK * PVOL;

    #pragma unroll
    for (int pre = 0; pre < 2; pre++) {
        unsigned sa = (unsigned)__cvta_generic_to_shared(sT + pre * (RANK * 136));
        #pragma unroll
        for (int i = 0; i < 4; i++) {
            int idx = t + 256 * i;
            int r = idx >> 4, j = idx & 15;
            cp_async16h(sa + (r * 136 + 8 * j) * 2,
                        Tbase + (size_t)r * PVOL + p_base + pre * 128 + 8 * j,
                        16, pef);
        }
        cp_commit();
    }

    #pragma unroll
    for (int i = t; i < RANK * COUT; i += 256) {
        int r = i >> 6, co = i & 63;
        sA[co * 72 + r] = __float2half(Uout[i]);
    }
    __syncthreads();

    int lane = t & 31, wid = t >> 5;
    int g = lane >> 2, tg = lane & 3;
    int c0 = (wid >> 1) * 16;
    int pW = (wid & 1) * 64;

    unsigned A[4][4];
    #pragma unroll
    for (int ks = 0; ks < 4; ks++) {
        int kk = ks * 16 + 2 * tg;
        A[ks][0] = *(const unsigned*)&sA[(c0 + g) * 72 + kk];
        A[ks][1] = *(const unsigned*)&sA[(c0 + g + 8) * 72 + kk];
        A[ks][2] = *(const unsigned*)&sA[(c0 + g) * 72 + kk + 8];
        A[ks][3] = *(const unsigned*)&sA[(c0 + g + 8) * 72 + kk + 8];
    }

    float bv0 = __ldg(&bias[c0 + g]);
    float bv1 = __ldg(&bias[c0 + g + 8]);

    int lm_row = lane & 15;
    int lm_col = 8 * (lane >> 4);

    #pragma unroll
    for (int tt = 0; tt < 4; tt++) {
        int p0 = p_base + tt * 128;

        if (tt < 3) cp_wait1(); else cp_wait0();
        __syncthreads();

        if (tt + 2 < 4) {
            unsigned sa = (unsigned)__cvta_generic_to_shared(
                sT + ((tt + 2) % 3) * (RANK * 136));
            #pragma unroll
            for (int i = 0; i < 4; i++) {
                int idx = t + 256 * i;
                int r = idx >> 4, j = idx & 15;
                cp_async16h(sa + (r * 136 + 8 * j) * 2,
                            Tbase + (size_t)r * PVOL + p0 + 256 + 8 * j,
                            16, pef);
            }
            cp_commit();
        }

        __half* cur = sT + (tt % 3) * (RANK * 136);

        float C[8][4];
        #pragma unroll
        for (int ni = 0; ni < 8; ni++)
            #pragma unroll
            for (int q = 0; q < 4; q++) C[ni][q] = 0.0f;

        unsigned cur_sa = (unsigned)__cvta_generic_to_shared(cur);

        #pragma unroll
        for (int ks = 0; ks < 4; ks++) {
            #pragma unroll
            for (int nj = 0; nj < 4; nj++) {
                unsigned b0, b1, b2, b3;
                unsigned addr = cur_sa +
                    ((ks * 16 + lm_row) * 136 + pW + nj * 16 + lm_col) * 2;
                ldsm_x4_trans(b0, b1, b2, b3, addr);
                mma_f16(C[2 * nj],     A[ks], b0, b1);
                mma_f16(C[2 * nj + 1], A[ks], b2, b3);
            }
        }

        #pragma unroll
        for (int ni = 0; ni < 8; ni++) {
            int p = p0 + pW + 8 * ni + 2 * tg;
            size_t o0 = (size_t)(b * COUT + c0 + g) * PVOL + p;
            size_t o1 = (size_t)(b * COUT + c0 + g + 8) * PVOL + p;
            st_f2_pol(&out[o0], C[ni][0] + bv0, C[ni][1] + bv0, pef);
            st_f2_pol(&out[o1], C[ni][2] + bv1, C[ni][3] + bv1, pef);
        }
    }
}

// ---------------------------------------------------------------------------
extern "C" void kernel_launch(void* const* d_in, const int* in_sizes, int n_in,
                              void* d_out, int out_size) {
    const float* x    = (const float*)d_in[0];
    const float* Uh   = (const float*)d_in[1];
    const float* Uw   = (const float*)d_in[2];
    const float* Ud   = (const float*)d_in[3];
    const float* Win  = (const float*)d_in[4];
    const float* Uout = (const float*)d_in[5];
    const float* bias = (const float*)d_in[6];
    float* out = (float*)d_out;

    const int k4_smem  = (64 * 72 + 3 * RANK * 136) * 2;        // 61440 B
    const int k23_smem = 3 * 4096 * 2 + 64 * 68 * 4;            // 41984 B
    cudaFuncSetAttribute(k4_mma, cudaFuncAttributeMaxDynamicSharedMemorySize,
                         k4_smem);
    cudaFuncSetAttribute(k23_stream, cudaFuncAttributeMaxDynamicSharedMemorySize,
                         k23_smem);

    k1_mma<<<SB * 512, 256>>>(x, Win);
    k23_stream<<<SB * RANK * 8, 256, k23_smem>>>(Uh, Uw, Ud);
    k4_mma<<<SB * 512, 256, k4_smem>>>(Uout, bias, out);
}

// round 16
// speedup vs baseline: 1.1247x; 1.1247x over previous
#include <cuda_runtime.h>
#include <cuda_fp16.h>

#define SB   2
#define CIN  32
#define COUT 64
#define RANK 64
#define S    64
#define PVOL (S*S*S)   // 262144
#define NT_TILES (SB * 2048)   // 4096 work items (128-p tiles) for k1/k4

// Scratch (alloc-free rule: device globals). fp16: 67 MB each.
__device__ __half g_bufA[(size_t)SB * RANK * PVOL];
__device__ __half g_bufB[(size_t)SB * RANK * PVOL];

// ---------------------------------------------------------------------------
// helpers
// ---------------------------------------------------------------------------
__device__ __forceinline__ unsigned f2tf(float f) {
    unsigned u;
    asm("cvt.rna.tf32.f32 %0, %1;" : "=r"(u) : "f"(f));
    return u;
}

__device__ __forceinline__ void mma_tf32(float c[4], const unsigned a[4],
                                         const unsigned b0, const unsigned b1) {
    asm volatile(
        "mma.sync.aligned.m16n8k8.row.col.f32.tf32.tf32.f32 "
        "{%0,%1,%2,%3}, {%4,%5,%6,%7}, {%8,%9}, {%0,%1,%2,%3};"
        : "+f"(c[0]), "+f"(c[1]), "+f"(c[2]), "+f"(c[3])
        : "r"(a[0]), "r"(a[1]), "r"(a[2]), "r"(a[3]), "r"(b0), "r"(b1));
}

__device__ __forceinline__ void mma_f16(float c[4], const unsigned a[4],
                                        const unsigned b0, const unsigned b1) {
    asm volatile(
        "mma.sync.aligned.m16n8k16.row.col.f32.f16.f16.f32 "
        "{%0,%1,%2,%3}, {%4,%5,%6,%7}, {%8,%9}, {%0,%1,%2,%3};"
        : "+f"(c[0]), "+f"(c[1]), "+f"(c[2]), "+f"(c[3])
        : "r"(a[0]), "r"(a[1]), "r"(a[2]), "r"(a[3]), "r"(b0), "r"(b1));
}

__device__ __forceinline__ void ldsm_x4_trans(unsigned& r0, unsigned& r1,
                                              unsigned& r2, unsigned& r3,
                                              unsigned saddr) {
    asm volatile(
        "ldmatrix.sync.aligned.m8n8.x4.trans.shared.b16 {%0,%1,%2,%3}, [%4];"
        : "=r"(r0), "=r"(r1), "=r"(r2), "=r"(r3) : "r"(saddr));
}

// L2 policies
__device__ __forceinline__ unsigned long long pol_ef() {
    unsigned long long p;
    asm("createpolicy.fractional.L2::evict_first.b64 %0, 1.0;" : "=l"(p));
    return p;
}
__device__ __forceinline__ unsigned long long pol_el() {
    unsigned long long p;
    asm("createpolicy.fractional.L2::evict_last.b64 %0, 1.0;" : "=l"(p));
    return p;
}

// cp.async with explicit src-size + L2 cache policy
__device__ __forceinline__ void cp_async16h(unsigned saddr, const void* gptr,
                                            int sz, unsigned long long pol) {
    asm volatile(
        "cp.async.cg.shared.global.L2::cache_hint [%0], [%1], 16, %2, %3;\n"
        :: "r"(saddr), "l"(gptr), "r"(sz), "l"(pol));
}
__device__ __forceinline__ void cp_commit() {
    asm volatile("cp.async.commit_group;\n");
}
__device__ __forceinline__ void cp_wait0() {
    asm volatile("cp.async.wait_group 0;\n");
}

// policy-register stores (cache_hint form — valid for all widths)
__device__ __forceinline__ void st_b32_pol(void* addr, unsigned v,
                                           unsigned long long pol) {
    asm volatile("st.global.L2::cache_hint.b32 [%0], %1, %2;"
                 :: "l"(addr), "r"(v), "l"(pol));
}
__device__ __forceinline__ void st_b64_pol(void* addr, unsigned long long v,
                                           unsigned long long pol) {
    asm volatile("st.global.L2::cache_hint.b64 [%0], %1, %2;"
                 :: "l"(addr), "l"(v), "l"(pol));
}
__device__ __forceinline__ void st_f2_pol(void* addr, float a, float b,
                                          unsigned long long pol) {
    asm volatile("st.global.L2::cache_hint.v2.f32 [%0], {%1, %2}, %3;"
                 :: "l"(addr), "f"(a), "f"(b), "l"(pol));
}

// ---------------------------------------------------------------------------
// K1 (tf32, persistent grid-stride, 2-buffer cp.async ping-pong)
// y[b,r,p] = sum_c Win[c,r] * x[b,c,p] -> fp16 (evict_last)
// Work item = one 128-p tile; weights/A-frags loaded once per block.
// ---------------------------------------------------------------------------
__global__ void __launch_bounds__(256) k1_mma(const float* __restrict__ x,
                                              const float* __restrict__ Win) {
    __shared__ unsigned sW[CIN * 72];      // tf32 weights [c][r], ld=72
    __shared__ unsigned sX[2][CIN * 136];  // raw fp32 bits x tiles [c][p]

    int t = threadIdx.x;
    unsigned long long pef = pol_ef();
    unsigned long long pel = pol_el();

    int w0 = blockIdx.x;

    // prologue: issue fill for first work item into buf 0
    if (w0 < NT_TILES) {
        int b = w0 >> 11, poff = (w0 & 2047) << 7;
        const float* xb = x + (size_t)b * CIN * PVOL;
        unsigned sa = (unsigned)__cvta_generic_to_shared(&sX[0][0]);
        #pragma unroll
        for (int i = 0; i < 4; i++) {
            int idx = t + 256 * i;
            int c = idx >> 5, j = idx & 31;
            cp_async16h(sa + (c * 136 + 4 * j) * 4,
                        xb + (size_t)c * PVOL + poff + 4 * j, 16, pef);
        }
        cp_commit();
    }

    // weights -> smem (once per block)
    {
        const float4* W4 = (const float4*)Win;
        for (int i = t; i < CIN * RANK / 4; i += 256) {
            int c = i >> 4, r4 = i & 15;
            float4 v = W4[i];
            unsigned* dst = &sW[c * 72 + 4 * r4];
            dst[0] = f2tf(v.x); dst[1] = f2tf(v.y);
            dst[2] = f2tf(v.z); dst[3] = f2tf(v.w);
        }
    }
    cp_wait0();
    __syncthreads();

    int lane = t & 31, wid = t >> 5;
    int g = lane >> 2, tg = lane & 3;
    int r0 = (wid & 1) * 32;       // M offset: 2 groups of 32 ranks
    int pW = (wid >> 1) * 32;      // N offset: 4 groups of 32 positions

    // A fragments loaded once per block
    unsigned A[4][2][4];
    #pragma unroll
    for (int ks = 0; ks < 4; ks++)
        #pragma unroll
        for (int mm = 0; mm < 2; mm++) {
            int rm = r0 + 16 * mm;
            A[ks][mm][0] = sW[(ks * 8 + tg) * 72 + rm + g];
            A[ks][mm][1] = sW[(ks * 8 + tg) * 72 + rm + g + 8];
            A[ks][mm][2] = sW[(ks * 8 + tg + 4) * 72 + rm + g];
            A[ks][mm][3] = sW[(ks * 8 + tg + 4) * 72 + rm + g + 8];
        }

    int buf = 0;
    for (int w = w0; w < NT_TILES; w += gridDim.x) {
        int b    = w >> 11;
        int poff = (w & 2047) << 7;
        int wn   = w + gridDim.x;

        // prefetch next work item into the other buffer
        if (wn < NT_TILES) {
            int bn = wn >> 11, pn = (wn & 2047) << 7;
            const float* xb2 = x + (size_t)bn * CIN * PVOL;
            unsigned sa = (unsigned)__cvta_generic_to_shared(&sX[buf ^ 1][0]);
            #pragma unroll
            for (int i = 0; i < 4; i++) {
                int idx = t + 256 * i;
                int c = idx >> 5, j = idx & 31;
                cp_async16h(sa + (c * 136 + 4 * j) * 4,
                            xb2 + (size_t)c * PVOL + pn + 4 * j, 16, pef);
            }
            cp_commit();
        }

        const unsigned* cur = sX[buf];

        float C[2][4][4];
        #pragma unroll
        for (int mm = 0; mm < 2; mm++)
            #pragma unroll
            for (int ni = 0; ni < 4; ni++)
                #pragma unroll
                for (int q = 0; q < 4; q++) C[mm][ni][q] = 0.0f;

        #pragma unroll
        for (int ks = 0; ks < 4; ks++) {
            #pragma unroll
            for (int ni = 0; ni < 4; ni++) {
                unsigned b0 = cur[(ks * 8 + tg) * 136 + pW + 8 * ni + g];
                unsigned b1 = cur[(ks * 8 + tg + 4) * 136 + pW + 8 * ni + g];
                mma_tf32(C[0][ni], A[ks][0], b0, b1);
                mma_tf32(C[1][ni], A[ks][1], b0, b1);
            }
        }

        #pragma unroll
        for (int mm = 0; mm < 2; mm++)
            #pragma unroll
            for (int ni = 0; ni < 4; ni++) {
                int p = poff + pW + 8 * ni + 2 * tg;
                int rm = r0 + 16 * mm;
                size_t o0 = (size_t)(b * RANK + rm + g) * PVOL + p;
                size_t o1 = (size_t)(b * RANK + rm + g + 8) * PVOL + p;
                __half2 v0 = __floats2half2_rn(C[mm][ni][0], C[mm][ni][1]);
                __half2 v1 = __floats2half2_rn(C[mm][ni][2], C[mm][ni][3]);
                st_b32_pol(&g_bufA[o0], *(unsigned*)&v0, pel);
                st_b32_pol(&g_bufA[o1], *(unsigned*)&v1, pel);
            }

        if (wn < NT_TILES) {
            cp_wait0();
            __syncthreads();
        }
        buf ^= 1;
    }
}

// ---------------------------------------------------------------------------
// K23 (streaming, cp.async ring, shuffle d-tap, L2 hints): fp16 planes.
// (unchanged — at its DRAM floor)
// ---------------------------------------------------------------------------
__global__ void __launch_bounds__(256) k23_stream(const float* __restrict__ Uh,
                                                  const float* __restrict__ Uw,
                                                  const float* __restrict__ Ud) {
    extern __shared__ float dsm[];
    __half* raw = (__half*)dsm;            // 3 planes x 4096 halves
    float* hq  = dsm + 3 * 4096 / 2;       // 64*68 fp32

    int blk = blockIdx.x;
    int hc = blk & 7;
    int r  = (blk >> 3) & 63;
    int b  = blk >> 9;
    int h0 = hc * 8;
    size_t rbase = (size_t)(b * RANK + r) * PVOL;
    int t = threadIdx.x;

    unsigned long long pef = pol_ef();
    unsigned long long pel = pol_el();

    float uh0 = __ldg(&Uh[r]), uh1 = __ldg(&Uh[64 + r]), uh2 = __ldg(&Uh[128 + r]);
    float uw0 = __ldg(&Uw[r]), uw1 = __ldg(&Uw[64 + r]), uw2 = __ldg(&Uw[128 + r]);
    float ud0 = __ldg(&Ud[r]), ud1 = __ldg(&Ud[64 + r]), ud2 = __ldg(&Ud[128 + r]);

    const float4 z4 = make_float4(0.f, 0.f, 0.f, 0.f);
    unsigned raw_sa = (unsigned)__cvta_generic_to_shared(raw);

    #pragma unroll
    for (int k = -1; k <= 1; k++) {
        int hp = h0 + k;
        int slot = (hp + 3) % 3;
        int sz = (hp >= 0 && hp < 64) ? 16 : 0;
        const __half* src = g_bufA + rbase + (size_t)hp * 4096;
        #pragma unroll
        for (int i = 0; i < 2; i++) {
            int q = t + i * 256;
            cp_async16h(raw_sa + (slot * 4096 + q * 8) * 2, src + q * 8, sz, pef);
        }
    }
    cp_commit();
    cp_wait0();
    __syncthreads();

    for (int hh = 0; hh < 8; hh++) {
        int h = h0 + hh;
        int sm_ = (h + 2) % 3;
        int s0  = h % 3;
        int sp  = (h + 1) % 3;

        // h-tap: raw(fp16) -> hq(fp32)
        #pragma unroll
        for (int i = 0; i < 4; i++) {
            int q = t + i * 256;
            int w = q >> 4, d4 = q & 15;
            __half2 m01 = *(__half2*)&raw[sm_ * 4096 + q * 4];
            __half2 m23 = *(__half2*)&raw[sm_ * 4096 + q * 4 + 2];
            __half2 c01 = *(__half2*)&raw[s0  * 4096 + q * 4];
            __half2 c23 = *(__half2*)&raw[s0  * 4096 + q * 4 + 2];
            __half2 p01 = *(__half2*)&raw[sp  * 4096 + q * 4];
            __half2 p23 = *(__half2*)&raw[sp  * 4096 + q * 4 + 2];
            float2 mA = __half22float2(m01), mB = __half22float2(m23);
            float2 cA = __half22float2(c01), cB = __half22float2(c23);
            float2 pA = __half22float2(p01), pB = __half22float2(p23);
            float4 o;
            o.x = uh0 * mA.x + uh1 * cA.x + uh2 * pA.x;
            o.y = uh0 * mA.y + uh1 * cA.y + uh2 * pA.y;
            o.z = uh0 * mB.x + uh1 * cB.x + uh2 * pB.x;
            o.w = uh0 * mB.y + uh1 * cB.y + uh2 * pB.y;
            *(float4*)&hq[w * 68 + d4 * 4] = o;
        }
        __syncthreads();   // hq ready; raw[sm_] now free

        if (hh < 7) {
            int hn = h + 2;
            int sz = (hn < 64) ? 16 : 0;
            const __half* src = g_bufA + rbase + (size_t)hn * 4096;
            #pragma unroll
            for (int i = 0; i < 2; i++) {
                int q = t + i * 256;
                cp_async16h(raw_sa + (sm_ * 4096 + q * 8) * 2, src + q * 8, sz, pef);
            }
            cp_commit();
        }

        // w-tap (regs) + shuffle d-tap -> fp16 gmem (evict_last)
        __half* Bo = g_bufB + rbase + (size_t)h * 4096;
        #pragma unroll
        for (int i = 0; i < 4; i++) {
            int q = t + i * 256;
            int w = q >> 4, d4 = q & 15;
            float4 c0 = *(const float4*)&hq[w * 68 + d4 * 4];
            float4 m = z4, p = z4;
            if (w > 0)  m = *(const float4*)&hq[(w - 1) * 68 + d4 * 4];
            if (w < 63) p = *(const float4*)&hq[(w + 1) * 68 + d4 * 4];
            float4 f;
            f.x = uw0 * m.x + uw1 * c0.x + uw2 * p.x;
            f.y = uw0 * m.y + uw1 * c0.y + uw2 * p.y;
            f.z = uw0 * m.z + uw1 * c0.z + uw2 * p.z;
            f.w = uw0 * m.w + uw1 * c0.w + uw2 * p.w;

            float lft = __shfl_up_sync(0xffffffffu, f.w, 1);
            float rgt = __shfl_down_sync(0xffffffffu, f.x, 1);
            if (d4 == 0)  lft = 0.f;
            if (d4 == 15) rgt = 0.f;

            __half2 lo = __floats2half2_rn(ud0 * lft + ud1 * f.x + ud2 * f.y,
                                           ud0 * f.x + ud1 * f.y + ud2 * f.z);
            __half2 hi = __floats2half2_rn(ud0 * f.y + ud1 * f.z + ud2 * f.w,
                                           ud0 * f.z + ud1 * f.w + ud2 * rgt);
            unsigned long long pk =
                (unsigned long long)(*(unsigned*)&lo) |
                ((unsigned long long)(*(unsigned*)&hi) << 32);
            st_b64_pol(&Bo[q * 4], pk, pel);
        }

        if (hh < 7) cp_wait0();
        __syncthreads();   // raw slot refilled; hq reads done
    }
}

// ---------------------------------------------------------------------------
// K4 (fp16 HMMA + ldmatrix, persistent grid-stride, 2-buffer ping-pong)
// out = Uout^T * t + bias
// ---------------------------------------------------------------------------
__global__ void __launch_bounds__(256) k4_mma(const float* __restrict__ Uout,
                                              const float* __restrict__ bias,
                                              float* __restrict__ out) {
    extern __shared__ __half hsm[];
    __half* sA  = hsm;                 // [co=64][r], ld=72 halves
    __half* sT0 = hsm + 64 * 72;       // fp16 tiles [r][p], ld=136 halves
    __half* sT1 = sT0 + RANK * 136;

    int t = threadIdx.x;
    unsigned long long pef = pol_ef();

    int w0 = blockIdx.x;

    if (w0 < NT_TILES) {
        int b = w0 >> 11, poff = (w0 & 2047) << 7;
        const __half* Tb = g_bufB + (size_t)b * RANK * PVOL;
        unsigned sa = (unsigned)__cvta_generic_to_shared(sT0);
        #pragma unroll
        for (int i = 0; i < 4; i++) {
            int idx = t + 256 * i;
            int r = idx >> 4, j = idx & 15;
            cp_async16h(sa + (r * 136 + 8 * j) * 2,
                        Tb + (size_t)r * PVOL + poff + 8 * j, 16, pef);
        }
        cp_commit();
    }

    // weights -> smem (once per block): transpose Uout [r][co] -> sA[co][r] fp16
    #pragma unroll
    for (int i = t; i < RANK * COUT; i += 256) {
        int r = i >> 6, co = i & 63;
        sA[co * 72 + r] = __float2half(Uout[i]);
    }
    cp_wait0();
    __syncthreads();

    int lane = t & 31, wid = t >> 5;
    int g = lane >> 2, tg = lane & 3;
    int c0 = (wid >> 1) * 16;
    int pW = (wid & 1) * 64;

    unsigned A[4][4];
    #pragma unroll
    for (int ks = 0; ks < 4; ks++) {
        int kk = ks * 16 + 2 * tg;
        A[ks][0] = *(const unsigned*)&sA[(c0 + g) * 72 + kk];
        A[ks][1] = *(const unsigned*)&sA[(c0 + g + 8) * 72 + kk];
        A[ks][2] = *(const unsigned*)&sA[(c0 + g) * 72 + kk + 8];
        A[ks][3] = *(const unsigned*)&sA[(c0 + g + 8) * 72 + kk + 8];
    }

    float bv0 = __ldg(&bias[c0 + g]);
    float bv1 = __ldg(&bias[c0 + g + 8]);

    int lm_row = lane & 15;
    int lm_col = 8 * (lane >> 4);

    int buf = 0;
    for (int w = w0; w < NT_TILES; w += gridDim.x) {
        int b    = w >> 11;
        int poff = (w & 2047) << 7;
        int wn   = w + gridDim.x;

        if (wn < NT_TILES) {
            int bn = wn >> 11, pn = (wn & 2047) << 7;
            const __half* Tb2 = g_bufB + (size_t)bn * RANK * PVOL;
            unsigned sa = (unsigned)__cvta_generic_to_shared(buf ? sT0 : sT1);
            #pragma unroll
            for (int i = 0; i < 4; i++) {
                int idx = t + 256 * i;
                int r = idx >> 4, j = idx & 15;
                cp_async16h(sa + (r * 136 + 8 * j) * 2,
                            Tb2 + (size_t)r * PVOL + pn + 8 * j, 16, pef);
            }
            cp_commit();
        }

        __half* cur = buf ? sT1 : sT0;

        float C[8][4];
        #pragma unroll
        for (int ni = 0; ni < 8; ni++)
            #pragma unroll
            for (int q = 0; q < 4; q++) C[ni][q] = 0.0f;

        unsigned cur_sa = (unsigned)__cvta_generic_to_shared(cur);

        #pragma unroll
        for (int ks = 0; ks < 4; ks++) {
            #pragma unroll
            for (int nj = 0; nj < 4; nj++) {
                unsigned b0, b1, b2, b3;
                unsigned addr = cur_sa +
                    ((ks * 16 + lm_row) * 136 + pW + nj * 16 + lm_col) * 2;
                ldsm_x4_trans(b0, b1, b2, b3, addr);
                mma_f16(C[2 * nj],     A[ks], b0, b1);
                mma_f16(C[2 * nj + 1], A[ks], b2, b3);
            }
        }

        #pragma unroll
        for (int ni = 0; ni < 8; ni++) {
            int p = poff + pW + 8 * ni + 2 * tg;
            size_t o0 = (size_t)(b * COUT + c0 + g) * PVOL + p;
            size_t o1 = (size_t)(b * COUT + c0 + g + 8) * PVOL + p;
            st_f2_pol(&out[o0], C[ni][0] + bv0, C[ni][1] + bv0, pef);
            st_f2_pol(&out[o1], C[ni][2] + bv1, C[ni][3] + bv1, pef);
        }

        if (wn < NT_TILES) {
            cp_wait0();
            __syncthreads();
        }
        buf ^= 1;
    }
}

// ---------------------------------------------------------------------------
extern "C" void kernel_launch(void* const* d_in, const int* in_sizes, int n_in,
                              void* d_out, int out_size) {
    const float* x    = (const float*)d_in[0];
    const float* Uh   = (const float*)d_in[1];
    const float* Uw   = (const float*)d_in[2];
    const float* Ud   = (const float*)d_in[3];
    const float* Win  = (const float*)d_in[4];
    const float* Uout = (const float*)d_in[5];
    const float* bias = (const float*)d_in[6];
    float* out = (float*)d_out;

    const int k4_smem  = (64 * 72 + 2 * RANK * 136) * 2;        // 44032 B
    const int k23_smem = 3 * 4096 * 2 + 64 * 68 * 4;            // 41984 B
    cudaFuncSetAttribute(k4_mma, cudaFuncAttributeMaxDynamicSharedMemorySize,
                         k4_smem);
    cudaFuncSetAttribute(k23_stream, cudaFuncAttributeMaxDynamicSharedMemorySize,
                         k23_smem);

    // persistent grids: exactly one wave (occupancy-queried, capture-safe)
    int dev = 0, sms = 148;
    cudaGetDevice(&dev);
    cudaDeviceGetAttribute(&sms, cudaDevAttrMultiProcessorCount, dev);
    int bpm1 = 1, bpm4 = 1;
    cudaOccupancyMaxActiveBlocksPerMultiprocessor(&bpm1, k1_mma, 256, 0);
    cudaOccupancyMaxActiveBlocksPerMultiprocessor(&bpm4, k4_mma, 256, k4_smem);
    int g1 = bpm1 * sms; if (g1 > NT_TILES) g1 = NT_TILES;
    int g4 = bpm4 * sms; if (g4 > NT_TILES) g4 = NT_TILES;

    k1_mma<<<g1, 256>>>(x, Win);
    k23_stream<<<SB * RANK * 8, 256, k23_smem>>>(Uh, Uw, Ud);
    k4_mma<<<g4, 256, k4_smem>>>(Uout, bias, out);
}